// round 15
// baseline (speedup 1.0000x reference)
#include <cuda_runtime.h>
#include <cuda_bf16.h>
#include <cuda_fp16.h>
#include <math.h>

#define N_NODES 50000
#define N_EDGES 800000
#define FEAT    128
#define HEADS   8
#define CH      16

// ---------------- scratch (no allocs; referenced ONLY from device code) ----------
static __device__ __align__(16) __half   g_bufH[(size_t)N_NODES * FEAT];  // h (fp16)
static __device__ __align__(16) unsigned g_ah[(size_t)N_NODES * 64];      // agg out bf16-hi (packed pairs)
static __device__ __align__(16) unsigned g_al[(size_t)N_NODES * 64];      // agg out bf16-lo
static __device__ __align__(16) unsigned g_Wh[128 * 128];                 // prepacked W hi (frag-major)
static __device__ __align__(16) unsigned g_Wl[128 * 128];                 // prepacked W lo
static __device__ float g_alsrc[N_NODES * HEADS];
static __device__ float g_aldst[N_NODES * HEADS];
static __device__ int   g_rowptr[N_NODES + 1];
static __device__ int   g_cnt[N_NODES];
static __device__ int   g_fill[N_NODES];
static __device__ int   g_col[N_EDGES];
static __device__ int   g_incl[N_NODES];
static __device__ int   g_bsum[64];
static __device__ float g_gsum[16];
static __device__ int   g_is64;

__device__ __forceinline__ float lrelu02(float x) { return x > 0.f ? x : 0.2f * x; }
__device__ __forceinline__ float elu1(float x)    { return x > 0.f ? x : (__expf(x) - 1.f); }
__device__ __forceinline__ int   clampN(int v)    { return v < 0 ? 0 : (v >= N_NODES ? N_NODES - 1 : v); }

__device__ __forceinline__ int load_src(const void* eiv, int e) {
    return clampN(g_is64 ? (int)((const long long*)eiv)[e] : ((const int*)eiv)[e]);
}
__device__ __forceinline__ int load_dst(const void* eiv, int e) {
    return clampN(g_is64 ? (int)((const long long*)eiv)[N_EDGES + e]
                         : ((const int*)eiv)[N_EDGES + e]);
}

// ---------------- bf16 helpers ----------------
__device__ __forceinline__ void split_bf(float x, float& hi, float& lo) {
    __nv_bfloat16 h = __float2bfloat16(x);
    hi = __bfloat162float(h);
    lo = x - hi;
}
__device__ __forceinline__ unsigned pack_bf2(float x0, float x1) {
    __nv_bfloat162 t = __floats2bfloat162_rn(x0, x1);
    return *(unsigned*)&t;
}
__device__ __forceinline__ void mma16(float* d,
                                      unsigned a0, unsigned a1, unsigned a2, unsigned a3,
                                      unsigned b0, unsigned b1) {
    asm volatile(
        "mma.sync.aligned.m16n8k16.row.col.f32.bf16.bf16.f32 "
        "{%0,%1,%2,%3}, {%4,%5,%6,%7}, {%8,%9}, {%0,%1,%2,%3};\n"
        : "+f"(d[0]), "+f"(d[1]), "+f"(d[2]), "+f"(d[3])
        : "r"(a0), "r"(a1), "r"(a2), "r"(a3), "r"(b0), "r"(b1));
}

// ---------------- CSR build ----------------
__global__ void k_zero(const unsigned int* __restrict__ w) {
    int i = blockIdx.x * blockDim.x + threadIdx.x;
    if (i < N_NODES) { g_cnt[i] = 0; g_fill[i] = 0; }
    if (i < 16) g_gsum[i] = 0.f;
    if (blockIdx.x == 0) {
        __shared__ unsigned int sh[256];
        int t = threadIdx.x;
        sh[t] = w[2 * t + 1] | w[2 * (t + 256) + 1];
        __syncthreads();
        for (int off = 128; off > 0; off >>= 1) {
            if (t < off) sh[t] |= sh[t + off];
            __syncthreads();
        }
        if (t == 0) g_is64 = (sh[0] == 0u) ? 1 : 0;
    }
}

__global__ void k_count(const void* __restrict__ eiv) {
    int e = blockIdx.x * blockDim.x + threadIdx.x;
    if (e >= N_EDGES) return;
    atomicAdd(&g_cnt[load_dst(eiv, e)], 1);
}

__global__ void k_scan1() {
    __shared__ int sh[1024];
    int t = threadIdx.x;
    int g = blockIdx.x * 1024 + t;
    int v = (g < N_NODES) ? g_cnt[g] : 0;
    sh[t] = v;
    __syncthreads();
    for (int off = 1; off < 1024; off <<= 1) {
        int add = (t >= off) ? sh[t - off] : 0;
        __syncthreads();
        sh[t] += add;
        __syncthreads();
    }
    if (g < N_NODES) g_incl[g] = sh[t];
    if (t == 1023) g_bsum[blockIdx.x] = sh[1023];
}

__global__ void k_scan3() {
    __shared__ int pre[64];
    if (threadIdx.x == 0) {
        int acc = 0;
        for (int j = 0; j < 49; j++) { pre[j] = acc; acc += g_bsum[j]; }
    }
    __syncthreads();
    int i = blockIdx.x * blockDim.x + threadIdx.x;
    if (i >= N_NODES) return;
    g_rowptr[i + 1] = g_incl[i] + pre[i >> 10];
    if (i == 0) g_rowptr[0] = 0;
}

__global__ void k_scatter(const void* __restrict__ eiv) {
    int e = blockIdx.x * blockDim.x + threadIdx.x;
    if (e >= N_EDGES) return;
    int d = load_dst(eiv, e);
    int pos = g_rowptr[d] + atomicAdd(&g_fill[d], 1);
    g_col[pos] = load_src(eiv, e);
}

// ---------------- W pre-pack: fp32 [K][128] -> frag-major bf16 hi/lo pairs --------
// g_Wh[kt*1024 + row*128 + idx] = pack(bf16hi(W[2k2][n]), bf16hi(W[2k2+1][n]))
// where k2 = kt*8+row, idx = (n&7)*16 + (n>>3).
__global__ void k_packW(const float* __restrict__ W, int K) {
    int u = blockIdx.x * blockDim.x + threadIdx.x;   // over (K/2)*128
    if (u >= (K >> 1) * 128) return;
    int k2 = u >> 7;
    int n  = u & 127;
    float w0 = W[(size_t)(2 * k2) * 128 + n];
    float w1 = W[(size_t)(2 * k2 + 1) * 128 + n];
    float h0, l0, h1, l1;
    split_bf(w0, h0, l0);
    split_bf(w1, h1, l1);
    int kt  = k2 >> 3;
    int row = k2 & 7;
    int idx = (n & 7) * 16 + (n >> 3);
    g_Wh[kt * 1024 + row * 128 + idx] = pack_bf2(h0, h1);
    g_Wl[kt * 1024 + row * 128 + idx] = pack_bf2(l0, l1);
}

// ---------------- tensor-core GEMM (3xBF16 k16; prepacked W, prepacked A for SRC=1)
// h = A @ W written fp16 to g_bufH; fused logits fp32.
// BM=128, BN=128, BK=16; 8 warps, warp w owns rows w*16..w*16+15, all 128 cols.
template <int SRC>
__global__ __launch_bounds__(256, 2) void k_gemm(const float* __restrict__ Ain,
                                                 const float* __restrict__ a_src,
                                                 const float* __restrict__ a_dst,
                                                 int M, int K) {
    __shared__ __align__(16) __nv_bfloat16 AhS[128 * 40];
    __shared__ __align__(16) __nv_bfloat16 AlS[128 * 40];
    __shared__ __align__(16) unsigned      WhP[8 * 132];
    __shared__ __align__(16) unsigned      WlP[8 * 132];

    const int tid  = threadIdx.x;
    const int lane = tid & 31;
    const int warp = tid >> 5;
    const int q    = lane & 3;
    const int g    = lane >> 2;
    const int wrow = warp * 16;
    const int row0 = blockIdx.x * 128;

    float d[16][4];
#pragma unroll
    for (int j = 0; j < 16; j++)
#pragma unroll
        for (int i = 0; i < 4; i++) d[j][i] = 0.f;

    const int a_row = tid >> 1;
    const int a_kb  = (tid & 1) * 8;    // bf16 element offset (8 elems = 4 uints)
    const int gr    = row0 + a_row;
    const bool gok  = (gr < M);
    const int nkt   = K >> 4;

    // prologue prefetch (tile 0)
    uint4 pa_h = make_uint4(0, 0, 0, 0), pa_l = pa_h;
    float4 av0, av1;
    if (SRC == 0) {
        av0 = make_float4(0.f, 0.f, 0.f, 0.f); av1 = av0;
        if (gok) {
            av0 = *(const float4*)&Ain[(size_t)gr * K + a_kb];
            av1 = *(const float4*)&Ain[(size_t)gr * K + a_kb + 4];
        }
    } else {
        if (gok) {
            pa_h = *(const uint4*)&g_ah[(size_t)gr * 64 + (tid & 1) * 4];
            pa_l = *(const uint4*)&g_al[(size_t)gr * 64 + (tid & 1) * 4];
        }
    }
    uint4 pw_h = *(const uint4*)&g_Wh[tid * 4];
    uint4 pw_l = *(const uint4*)&g_Wl[tid * 4];

    for (int kt = 0; kt < nkt; kt++) {
        // ---- stage A ----
        if (SRC == 0) {
            float f[8] = {av0.x, av0.y, av0.z, av0.w, av1.x, av1.y, av1.z, av1.w};
            float hi[8], lo[8];
#pragma unroll
            for (int i = 0; i < 8; i++) split_bf(f[i], hi[i], lo[i]);
            *(uint4*)&AhS[a_row * 40 + a_kb] =
                make_uint4(pack_bf2(hi[0], hi[1]), pack_bf2(hi[2], hi[3]),
                           pack_bf2(hi[4], hi[5]), pack_bf2(hi[6], hi[7]));
            *(uint4*)&AlS[a_row * 40 + a_kb] =
                make_uint4(pack_bf2(lo[0], lo[1]), pack_bf2(lo[2], lo[3]),
                           pack_bf2(lo[4], lo[5]), pack_bf2(lo[6], lo[7]));
        } else {
            *(uint4*)&AhS[a_row * 40 + a_kb] = pa_h;
            *(uint4*)&AlS[a_row * 40 + a_kb] = pa_l;
        }
        // ---- stage W (plain copies; frag-major already) ----
        *(uint4*)&WhP[(tid >> 5) * 132 + (tid & 31) * 4] = pw_h;
        *(uint4*)&WlP[(tid >> 5) * 132 + (tid & 31) * 4] = pw_l;
        __syncthreads();

        // prefetch next tile
        if (kt + 1 < nkt) {
            int ktn = kt + 1;
            if (SRC == 0) {
                int k0g = ktn << 4;
                av0 = make_float4(0.f, 0.f, 0.f, 0.f); av1 = av0;
                if (gok) {
                    av0 = *(const float4*)&Ain[(size_t)gr * K + k0g + a_kb];
                    av1 = *(const float4*)&Ain[(size_t)gr * K + k0g + a_kb + 4];
                }
            } else {
                pa_h = make_uint4(0, 0, 0, 0); pa_l = pa_h;
                if (gok) {
                    pa_h = *(const uint4*)&g_ah[(size_t)gr * 64 + ktn * 8 + (tid & 1) * 4];
                    pa_l = *(const uint4*)&g_al[(size_t)gr * 64 + ktn * 8 + (tid & 1) * 4];
                }
            }
            pw_h = *(const uint4*)&g_Wh[ktn * 1024 + tid * 4];
            pw_l = *(const uint4*)&g_Wl[ktn * 1024 + tid * 4];
        }

        // ---- compute one k16 step ----
        {
            unsigned ah0 = *(const unsigned*)&AhS[(wrow + g) * 40 + 2 * q];
            unsigned ah1 = *(const unsigned*)&AhS[(wrow + g + 8) * 40 + 2 * q];
            unsigned ah2 = *(const unsigned*)&AhS[(wrow + g) * 40 + 2 * q + 8];
            unsigned ah3 = *(const unsigned*)&AhS[(wrow + g + 8) * 40 + 2 * q + 8];
            unsigned al0 = *(const unsigned*)&AlS[(wrow + g) * 40 + 2 * q];
            unsigned al1 = *(const unsigned*)&AlS[(wrow + g + 8) * 40 + 2 * q];
            unsigned al2 = *(const unsigned*)&AlS[(wrow + g) * 40 + 2 * q + 8];
            unsigned al3 = *(const unsigned*)&AlS[(wrow + g + 8) * 40 + 2 * q + 8];
#pragma unroll
            for (int c = 0; c < 4; c++) {
                uint4 vh0 = *(const uint4*)&WhP[q * 132 + g * 16 + 4 * c];
                uint4 vh1 = *(const uint4*)&WhP[(q + 4) * 132 + g * 16 + 4 * c];
                uint4 vl0 = *(const uint4*)&WlP[q * 132 + g * 16 + 4 * c];
                uint4 vl1 = *(const uint4*)&WlP[(q + 4) * 132 + g * 16 + 4 * c];
                const unsigned* b0h = (const unsigned*)&vh0;
                const unsigned* b1h = (const unsigned*)&vh1;
                const unsigned* b0l = (const unsigned*)&vl0;
                const unsigned* b1l = (const unsigned*)&vl1;
#pragma unroll
                for (int e = 0; e < 4; e++) {
                    const int j = c * 4 + e;
                    mma16(d[j], ah0, ah1, ah2, ah3, b0h[e], b1h[e]);
                    mma16(d[j], al0, al1, al2, al3, b0h[e], b1h[e]);
                    mma16(d[j], ah0, ah1, ah2, ah3, b0l[e], b1l[e]);
                }
            }
        }
        __syncthreads();
    }

    const int r0 = row0 + wrow + g;
    const int r1 = r0 + 8;

    // write h as fp16 (only the gather reads h)
#pragma unroll
    for (int j = 0; j < 16; j++) {
        int col = j * 8 + 2 * q;
        if (r0 < M) *(__half2*)&g_bufH[(size_t)r0 * 128 + col] = __floats2half2_rn(d[j][0], d[j][1]);
        if (r1 < M) *(__half2*)&g_bufH[(size_t)r1 * 128 + col] = __floats2half2_rn(d[j][2], d[j][3]);
    }

    // fused attention logits (fp32 accumulators)
#pragma unroll
    for (int hd = 0; hd < 8; hd++) {
        float ss0 = 0.f, ds0 = 0.f, ss1 = 0.f, ds1 = 0.f;
#pragma unroll
        for (int jj = 0; jj < 2; jj++) {
            int j = hd * 2 + jj;
            int c = jj * 8 + 2 * q;
            float as0 = a_src[hd * CH + c], as1 = a_src[hd * CH + c + 1];
            float ad0 = a_dst[hd * CH + c], ad1 = a_dst[hd * CH + c + 1];
            ss0 += d[j][0] * as0 + d[j][1] * as1;
            ds0 += d[j][0] * ad0 + d[j][1] * ad1;
            ss1 += d[j][2] * as0 + d[j][3] * as1;
            ds1 += d[j][2] * ad0 + d[j][3] * ad1;
        }
        ss0 += __shfl_xor_sync(0xffffffffu, ss0, 1);
        ss0 += __shfl_xor_sync(0xffffffffu, ss0, 2);
        ds0 += __shfl_xor_sync(0xffffffffu, ds0, 1);
        ds0 += __shfl_xor_sync(0xffffffffu, ds0, 2);
        ss1 += __shfl_xor_sync(0xffffffffu, ss1, 1);
        ss1 += __shfl_xor_sync(0xffffffffu, ss1, 2);
        ds1 += __shfl_xor_sync(0xffffffffu, ds1, 1);
        ds1 += __shfl_xor_sync(0xffffffffu, ds1, 2);
        if (q == 0) {
            if (r0 < M) { g_alsrc[r0 * 8 + hd] = ss0; g_aldst[r0 * 8 + hd] = ds0; }
            if (r1 < M) { g_alsrc[r1 * 8 + hd] = ss1; g_aldst[r1 * 8 + hd] = ds1; }
        }
    }
}

// ---------------- per-node softmax + aggregation (lean loop, fp16 gather) ----------
__device__ __forceinline__ float4 hload4(int s, int lane) {
    uint2 raw = *(const uint2*)&g_bufH[(size_t)s * FEAT + lane * 4];
    float2 f0 = __half22float2(*(__half2*)&raw.x);
    float2 f1 = __half22float2(*(__half2*)&raw.y);
    return make_float4(f0.x, f0.y, f1.x, f1.y);
}

// MODE 0: write pre-split bf16 hi/lo (g_ah/g_al) for the next GEMM
// MODE 1: mean over heads + bias -> d_out; fused anomaly head
template <int MODE>
__global__ void k_agg(const float* __restrict__ bias, float* __restrict__ outp,
                      const float* __restrict__ an_w1, const float* __restrict__ an_b1,
                      const float* __restrict__ an_w2, const float* __restrict__ an_b2) {
    int gw = (blockIdx.x * blockDim.x + threadIdx.x) >> 5;
    if (gw >= N_NODES) return;
    int lane = threadIdx.x & 31;
    int d = gw;
    const int beg = g_rowptr[d], end = g_rowptr[d + 1];
    const int head = lane >> 2;

    const float adst = g_aldst[d * 8 + head];
    float den;
    float4 acc;
    {   // self loop
        float p = __expf(lrelu02(g_alsrc[d * 8 + head] + adst));
        den = p;
        float4 hv = hload4(d, lane);
        acc.x = hv.x * p; acc.y = hv.y * p; acc.z = hv.z * p; acc.w = hv.w * p;
    }
    int i = beg;
    for (; i + 4 <= end; i += 4) {
        int s0 = g_col[i], s1 = g_col[i + 1], s2 = g_col[i + 2], s3 = g_col[i + 3];
        float a0 = g_alsrc[s0 * 8 + head];
        float a1 = g_alsrc[s1 * 8 + head];
        float a2 = g_alsrc[s2 * 8 + head];
        float a3 = g_alsrc[s3 * 8 + head];
        float4 h0 = hload4(s0, lane);
        float4 h1 = hload4(s1, lane);
        float4 h2 = hload4(s2, lane);
        float4 h3 = hload4(s3, lane);
        float p0 = __expf(lrelu02(a0 + adst));
        float p1 = __expf(lrelu02(a1 + adst));
        float p2 = __expf(lrelu02(a2 + adst));
        float p3 = __expf(lrelu02(a3 + adst));
        den += (p0 + p1) + (p2 + p3);
        acc.x += h0.x * p0 + h1.x * p1 + h2.x * p2 + h3.x * p3;
        acc.y += h0.y * p0 + h1.y * p1 + h2.y * p2 + h3.y * p3;
        acc.z += h0.z * p0 + h1.z * p1 + h2.z * p2 + h3.z * p3;
        acc.w += h0.w * p0 + h1.w * p1 + h2.w * p2 + h3.w * p3;
    }
    for (; i < end; i++) {
        int s = g_col[i];
        float p = __expf(lrelu02(g_alsrc[s * 8 + head] + adst));
        den += p;
        float4 hv = hload4(s, lane);
        acc.x += hv.x * p; acc.y += hv.y * p; acc.z += hv.z * p; acc.w += hv.w * p;
    }
    float inv = 1.f / den;
    acc.x *= inv; acc.y *= inv; acc.z *= inv; acc.w *= inv;

    if (MODE == 0) {
        float4 bb = *(const float4*)&bias[lane * 4];
        acc.x = elu1(acc.x + bb.x);
        acc.y = elu1(acc.y + bb.y);
        acc.z = elu1(acc.z + bb.z);
        acc.w = elu1(acc.w + bb.w);
        float hx, lx, hy, ly, hz, lz, hw, lw;
        split_bf(acc.x, hx, lx);
        split_bf(acc.y, hy, ly);
        split_bf(acc.z, hz, lz);
        split_bf(acc.w, hw, lw);
        uint2 vh = make_uint2(pack_bf2(hx, hy), pack_bf2(hz, hw));
        uint2 vl = make_uint2(pack_bf2(lx, ly), pack_bf2(lz, lw));
        *(uint2*)&g_ah[(size_t)d * 64 + lane * 2] = vh;
        *(uint2*)&g_al[(size_t)d * 64 + lane * 2] = vl;
    } else {
#pragma unroll
        for (int off = 4; off <= 16; off <<= 1) {
            acc.x += __shfl_xor_sync(0xffffffffu, acc.x, off);
            acc.y += __shfl_xor_sync(0xffffffffu, acc.y, off);
            acc.z += __shfl_xor_sync(0xffffffffu, acc.z, off);
            acc.w += __shfl_xor_sync(0xffffffffu, acc.w, off);
        }
        float4 bb = *(const float4*)&bias[(lane & 3) * 4];
        float4 r;
        r.x = acc.x * 0.125f + bb.x;
        r.y = acc.y * 0.125f + bb.y;
        r.z = acc.z * 0.125f + bb.z;
        r.w = acc.w * 0.125f + bb.w;
        if (lane < 4) *(float4*)&outp[(size_t)d * CH + lane * 4] = r;

        // fused anomaly head: 16 -> 32 relu -> 1 sigmoid
        float hv[16];
#pragma unroll
        for (int c = 0; c < 16; c++) {
            float comp = ((c & 3) == 0) ? r.x : ((c & 3) == 1) ? r.y
                        : ((c & 3) == 2) ? r.z : r.w;
            hv[c] = __shfl_sync(0xffffffffu, comp, c >> 2);
        }
        float t = an_b1[lane];
#pragma unroll
        for (int c = 0; c < 16; c++) t += hv[c] * an_w1[c * 32 + lane];
        float contrib = fmaxf(t, 0.f) * an_w2[lane];
#pragma unroll
        for (int off = 16; off >= 1; off >>= 1)
            contrib += __shfl_xor_sync(0xffffffffu, contrib, off);
        if (lane == 0)
            outp[800000 + d] = 1.f / (1.f + __expf(-(contrib + an_b2[0])));
    }
}

// ---------------- graph mean ----------------
__global__ void k_gsum(const float* __restrict__ hout) {
    __shared__ float sh[256];
    int tid = threadIdx.x;
    float s = 0.f;
    size_t total = (size_t)N_NODES * 16;
    size_t stride = (size_t)gridDim.x * 256;
    for (size_t idx = (size_t)blockIdx.x * 256 + tid; idx < total; idx += stride)
        s += hout[idx];
    sh[tid] = s;
    __syncthreads();
    for (int off = 128; off >= 16; off >>= 1) {
        if (tid < off) sh[tid] += sh[tid + off];
        __syncthreads();
    }
    if (tid < 16) atomicAdd(&g_gsum[tid], sh[tid]);
}

// ---------------- graph classifier ----------------
__global__ void k_final(const float* __restrict__ w1, const float* __restrict__ b1,
                        const float* __restrict__ w2, const float* __restrict__ b2,
                        float* __restrict__ out) {
    __shared__ float emb[16];
    __shared__ float hid[64];
    int t = threadIdx.x;
    if (t < 16) {
        float e = g_gsum[t] * (1.f / (float)N_NODES);
        emb[t] = e;
        out[850000 + t] = e;
    }
    __syncthreads();
    float s = b1[t];
#pragma unroll
    for (int c = 0; c < 16; c++) s += emb[c] * w1[c * 64 + t];
    hid[t] = fmaxf(s, 0.f);
    __syncthreads();
    if (t < 2) {
        float r = b2[t];
#pragma unroll
        for (int u = 0; u < 64; u++) r += hid[u] * w2[u * 2 + t];
        out[850016 + t] = r;
    }
}

// ---------------- launch ----------------
extern "C" void kernel_launch(void* const* d_in, const int* in_sizes, int n_in,
                              void* d_out, int out_size) {
    const float* x      = (const float*)d_in[0];
    const void*  ei     = d_in[1];
    const float* W1     = (const float*)d_in[2];
    const float* a1s    = (const float*)d_in[3];
    const float* a1d    = (const float*)d_in[4];
    const float* b1     = (const float*)d_in[5];
    const float* W2     = (const float*)d_in[6];
    const float* a2s    = (const float*)d_in[7];
    const float* a2d    = (const float*)d_in[8];
    const float* b2     = (const float*)d_in[9];
    const float* W3     = (const float*)d_in[10];
    const float* a3s    = (const float*)d_in[11];
    const float* a3d    = (const float*)d_in[12];
    const float* b3     = (const float*)d_in[13];
    const float* cls_w1 = (const float*)d_in[14];
    const float* cls_b1 = (const float*)d_in[15];
    const float* cls_w2 = (const float*)d_in[16];
    const float* cls_b2 = (const float*)d_in[17];
    const float* an_w1  = (const float*)d_in[18];
    const float* an_b1  = (const float*)d_in[19];
    const float* an_w2  = (const float*)d_in[20];
    const float* an_b2  = (const float*)d_in[21];
    float* out = (float*)d_out;

    const int TB = 256;
    const int nodeBlocks = (N_NODES + TB - 1) / TB;
    const int edgeBlocks = (N_EDGES + TB - 1) / TB;
    const int aggBlocks  = (N_NODES * 32 + TB - 1) / TB;
    const int gemmBlocks = (N_NODES + 127) / 128;  // 391
    const int nchunks    = (N_NODES + 1023) / 1024;

    // layer 1 (gemm1 kept in absolute launch slot #4 for profiling)
    k_packW<<<64, TB>>>(W1, 256);                              // 16384 threads
    k_zero<<<nodeBlocks, TB>>>((const unsigned int*)ei);
    k_count<<<edgeBlocks, TB>>>(ei);
    k_gemm<0><<<gemmBlocks, TB>>>(x, a1s, a1d, N_NODES, 256);  // profiled
    k_scan1<<<nchunks, 1024>>>();
    k_scan3<<<nodeBlocks, TB>>>();
    k_scatter<<<edgeBlocks, TB>>>(ei);
    k_agg<0><<<aggBlocks, TB>>>(b1, nullptr, nullptr, nullptr, nullptr, nullptr);

    // layer 2
    k_packW<<<32, TB>>>(W2, 128);
    k_gemm<1><<<gemmBlocks, TB>>>(nullptr, a2s, a2d, N_NODES, 128);
    k_agg<0><<<aggBlocks, TB>>>(b2, nullptr, nullptr, nullptr, nullptr, nullptr);

    // layer 3
    k_packW<<<32, TB>>>(W3, 128);
    k_gemm<1><<<gemmBlocks, TB>>>(nullptr, a3s, a3d, N_NODES, 128);
    k_agg<1><<<aggBlocks, TB>>>(b3, out, an_w1, an_b1, an_w2, an_b2);

    // heads
    k_gsum<<<64, TB>>>(out);
    k_final<<<1, 64>>>(cls_w1, cls_b1, cls_w2, cls_b2, out);
}

// round 16
// speedup vs baseline: 1.0304x; 1.0304x over previous
#include <cuda_runtime.h>
#include <cuda_bf16.h>
#include <cuda_fp16.h>
#include <math.h>

#define N_NODES 50000
#define N_EDGES 800000
#define FEAT    128
#define HEADS   8
#define CH      16

// ---------------- scratch (no allocs; referenced ONLY from device code) ----------
static __device__ __align__(16) __half   g_bufH[(size_t)N_NODES * FEAT];  // h (fp16)
static __device__ __align__(16) float    g_bufB[(size_t)N_NODES * FEAT];  // agg out (fp32)
static __device__ __align__(16) unsigned g_Wh[128 * 128];                 // prepacked W hi
static __device__ __align__(16) unsigned g_Wl[128 * 128];                 // prepacked W lo
static __device__ float g_alsrc[N_NODES * HEADS];
static __device__ float g_aldst[N_NODES * HEADS];
static __device__ int   g_rowptr[N_NODES + 1];
static __device__ int   g_cnt[N_NODES];
static __device__ int   g_fill[N_NODES];
static __device__ int   g_col[N_EDGES];
static __device__ int   g_incl[N_NODES];
static __device__ int   g_bsum[64];
static __device__ float g_gsum[16];
static __device__ int   g_is64;

__device__ __forceinline__ float lrelu02(float x) { return x > 0.f ? x : 0.2f * x; }
__device__ __forceinline__ float elu1(float x)    { return x > 0.f ? x : (__expf(x) - 1.f); }
__device__ __forceinline__ int   clampN(int v)    { return v < 0 ? 0 : (v >= N_NODES ? N_NODES - 1 : v); }

__device__ __forceinline__ int load_src(const void* eiv, int e) {
    return clampN(g_is64 ? (int)((const long long*)eiv)[e] : ((const int*)eiv)[e]);
}
__device__ __forceinline__ int load_dst(const void* eiv, int e) {
    return clampN(g_is64 ? (int)((const long long*)eiv)[N_EDGES + e]
                         : ((const int*)eiv)[N_EDGES + e]);
}

// ---------------- bf16 helpers ----------------
__device__ __forceinline__ void split_bf(float x, float& hi, float& lo) {
    __nv_bfloat16 h = __float2bfloat16(x);
    hi = __bfloat162float(h);
    lo = x - hi;
}
__device__ __forceinline__ unsigned pack_bf2(float x0, float x1) {
    __nv_bfloat162 t = __floats2bfloat162_rn(x0, x1);
    return *(unsigned*)&t;
}
__device__ __forceinline__ void mma16(float* d,
                                      unsigned a0, unsigned a1, unsigned a2, unsigned a3,
                                      unsigned b0, unsigned b1) {
    asm volatile(
        "mma.sync.aligned.m16n8k16.row.col.f32.bf16.bf16.f32 "
        "{%0,%1,%2,%3}, {%4,%5,%6,%7}, {%8,%9}, {%0,%1,%2,%3};\n"
        : "+f"(d[0]), "+f"(d[1]), "+f"(d[2]), "+f"(d[3])
        : "r"(a0), "r"(a1), "r"(a2), "r"(a3), "r"(b0), "r"(b1));
}

// ---------------- CSR build ----------------
__global__ void k_zero(const unsigned int* __restrict__ w) {
    int i = blockIdx.x * blockDim.x + threadIdx.x;
    if (i < N_NODES) { g_cnt[i] = 0; g_fill[i] = 0; }
    if (i < 16) g_gsum[i] = 0.f;
    if (blockIdx.x == 0) {
        __shared__ unsigned int sh[256];
        int t = threadIdx.x;
        sh[t] = w[2 * t + 1] | w[2 * (t + 256) + 1];
        __syncthreads();
        for (int off = 128; off > 0; off >>= 1) {
            if (t < off) sh[t] |= sh[t + off];
            __syncthreads();
        }
        if (t == 0) g_is64 = (sh[0] == 0u) ? 1 : 0;
    }
}

__global__ void k_count(const void* __restrict__ eiv) {
    int e = blockIdx.x * blockDim.x + threadIdx.x;
    if (e >= N_EDGES) return;
    atomicAdd(&g_cnt[load_dst(eiv, e)], 1);
}

__global__ void k_scan1() {
    __shared__ int sh[1024];
    int t = threadIdx.x;
    int g = blockIdx.x * 1024 + t;
    int v = (g < N_NODES) ? g_cnt[g] : 0;
    sh[t] = v;
    __syncthreads();
    for (int off = 1; off < 1024; off <<= 1) {
        int add = (t >= off) ? sh[t - off] : 0;
        __syncthreads();
        sh[t] += add;
        __syncthreads();
    }
    if (g < N_NODES) g_incl[g] = sh[t];
    if (t == 1023) g_bsum[blockIdx.x] = sh[1023];
}

__global__ void k_scan3() {
    __shared__ int pre[64];
    if (threadIdx.x == 0) {
        int acc = 0;
        for (int j = 0; j < 49; j++) { pre[j] = acc; acc += g_bsum[j]; }
    }
    __syncthreads();
    int i = blockIdx.x * blockDim.x + threadIdx.x;
    if (i >= N_NODES) return;
    g_rowptr[i + 1] = g_incl[i] + pre[i >> 10];
    if (i == 0) g_rowptr[0] = 0;
}

__global__ void k_scatter(const void* __restrict__ eiv) {
    int e = blockIdx.x * blockDim.x + threadIdx.x;
    if (e >= N_EDGES) return;
    int d = load_dst(eiv, e);
    int pos = g_rowptr[d] + atomicAdd(&g_fill[d], 1);
    g_col[pos] = load_src(eiv, e);
}

// ---------------- W pre-pack: fp32 [K][128] -> frag-major bf16 hi/lo pairs --------
__global__ void k_packW(const float* __restrict__ W, int K) {
    int u = blockIdx.x * blockDim.x + threadIdx.x;
    if (u >= (K >> 1) * 128) return;
    int k2 = u >> 7;
    int n  = u & 127;
    float w0 = W[(size_t)(2 * k2) * 128 + n];
    float w1 = W[(size_t)(2 * k2 + 1) * 128 + n];
    float h0, l0, h1, l1;
    split_bf(w0, h0, l0);
    split_bf(w1, h1, l1);
    int kt  = k2 >> 3;
    int row = k2 & 7;
    int idx = (n & 7) * 16 + (n >> 3);
    g_Wh[kt * 1024 + row * 128 + idx] = pack_bf2(h0, h1);
    g_Wl[kt * 1024 + row * 128 + idx] = pack_bf2(l0, l1);
}

// ---------------- tensor-core GEMM (3xBF16 k16; prepacked W) ----------------
// h = A @ W written fp16 to g_bufH; fused logits fp32.
// BM=128, BN=128, BK=16; 8 warps, warp w owns rows w*16..w*16+15, all 128 cols.
template <int SRC>
__global__ __launch_bounds__(256, 2) void k_gemm(const float* __restrict__ Ain,
                                                 const float* __restrict__ a_src,
                                                 const float* __restrict__ a_dst,
                                                 int M, int K) {
    const float* __restrict__ A = (SRC == 0) ? Ain : (const float*)g_bufB;

    __shared__ __align__(16) __nv_bfloat16 AhS[128 * 40];
    __shared__ __align__(16) __nv_bfloat16 AlS[128 * 40];
    __shared__ __align__(16) unsigned      WhP[8 * 132];
    __shared__ __align__(16) unsigned      WlP[8 * 132];

    const int tid  = threadIdx.x;
    const int lane = tid & 31;
    const int warp = tid >> 5;
    const int q    = lane & 3;
    const int g    = lane >> 2;
    const int wrow = warp * 16;
    const int row0 = blockIdx.x * 128;

    float d[16][4];
#pragma unroll
    for (int j = 0; j < 16; j++)
#pragma unroll
        for (int i = 0; i < 4; i++) d[j][i] = 0.f;

    const int a_row = tid >> 1;
    const int a_kb  = (tid & 1) * 8;
    const int gr    = row0 + a_row;
    const bool gok  = (gr < M);
    const int nkt   = K >> 4;

    float4 av0 = make_float4(0.f, 0.f, 0.f, 0.f), av1 = av0;
    if (gok) {
        av0 = *(const float4*)&A[(size_t)gr * K + a_kb];
        av1 = *(const float4*)&A[(size_t)gr * K + a_kb + 4];
    }
    uint4 pw_h = *(const uint4*)&g_Wh[tid * 4];
    uint4 pw_l = *(const uint4*)&g_Wl[tid * 4];

    for (int kt = 0; kt < nkt; kt++) {
        // ---- stage A (split fp32 -> bf16 hi/lo) ----
        {
            float f[8] = {av0.x, av0.y, av0.z, av0.w, av1.x, av1.y, av1.z, av1.w};
            float hi[8], lo[8];
#pragma unroll
            for (int i = 0; i < 8; i++) split_bf(f[i], hi[i], lo[i]);
            *(uint4*)&AhS[a_row * 40 + a_kb] =
                make_uint4(pack_bf2(hi[0], hi[1]), pack_bf2(hi[2], hi[3]),
                           pack_bf2(hi[4], hi[5]), pack_bf2(hi[6], hi[7]));
            *(uint4*)&AlS[a_row * 40 + a_kb] =
                make_uint4(pack_bf2(lo[0], lo[1]), pack_bf2(lo[2], lo[3]),
                           pack_bf2(lo[4], lo[5]), pack_bf2(lo[6], lo[7]));
        }
        // ---- stage W (plain copies; frag-major already) ----
        *(uint4*)&WhP[(tid >> 5) * 132 + (tid & 31) * 4] = pw_h;
        *(uint4*)&WlP[(tid >> 5) * 132 + (tid & 31) * 4] = pw_l;
        __syncthreads();

        if (kt + 1 < nkt) {
            int k0g = (kt + 1) << 4;
            av0 = make_float4(0.f, 0.f, 0.f, 0.f); av1 = av0;
            if (gok) {
                av0 = *(const float4*)&A[(size_t)gr * K + k0g + a_kb];
                av1 = *(const float4*)&A[(size_t)gr * K + k0g + a_kb + 4];
            }
            pw_h = *(const uint4*)&g_Wh[(kt + 1) * 1024 + tid * 4];
            pw_l = *(const uint4*)&g_Wl[(kt + 1) * 1024 + tid * 4];
        }

        // ---- compute one k16 step ----
        {
            unsigned ah0 = *(const unsigned*)&AhS[(wrow + g) * 40 + 2 * q];
            unsigned ah1 = *(const unsigned*)&AhS[(wrow + g + 8) * 40 + 2 * q];
            unsigned ah2 = *(const unsigned*)&AhS[(wrow + g) * 40 + 2 * q + 8];
            unsigned ah3 = *(const unsigned*)&AhS[(wrow + g + 8) * 40 + 2 * q + 8];
            unsigned al0 = *(const unsigned*)&AlS[(wrow + g) * 40 + 2 * q];
            unsigned al1 = *(const unsigned*)&AlS[(wrow + g + 8) * 40 + 2 * q];
            unsigned al2 = *(const unsigned*)&AlS[(wrow + g) * 40 + 2 * q + 8];
            unsigned al3 = *(const unsigned*)&AlS[(wrow + g + 8) * 40 + 2 * q + 8];
#pragma unroll
            for (int c = 0; c < 4; c++) {
                uint4 vh0 = *(const uint4*)&WhP[q * 132 + g * 16 + 4 * c];
                uint4 vh1 = *(const uint4*)&WhP[(q + 4) * 132 + g * 16 + 4 * c];
                uint4 vl0 = *(const uint4*)&WlP[q * 132 + g * 16 + 4 * c];
                uint4 vl1 = *(const uint4*)&WlP[(q + 4) * 132 + g * 16 + 4 * c];
                const unsigned* b0h = (const unsigned*)&vh0;
                const unsigned* b1h = (const unsigned*)&vh1;
                const unsigned* b0l = (const unsigned*)&vl0;
                const unsigned* b1l = (const unsigned*)&vl1;
#pragma unroll
                for (int e = 0; e < 4; e++) {
                    const int j = c * 4 + e;
                    mma16(d[j], ah0, ah1, ah2, ah3, b0h[e], b1h[e]);
                    mma16(d[j], al0, al1, al2, al3, b0h[e], b1h[e]);
                    mma16(d[j], ah0, ah1, ah2, ah3, b0l[e], b1l[e]);
                }
            }
        }
        __syncthreads();
    }

    const int r0 = row0 + wrow + g;
    const int r1 = r0 + 8;

    // write h as fp16 (only the gather reads h)
#pragma unroll
    for (int j = 0; j < 16; j++) {
        int col = j * 8 + 2 * q;
        if (r0 < M) *(__half2*)&g_bufH[(size_t)r0 * 128 + col] = __floats2half2_rn(d[j][0], d[j][1]);
        if (r1 < M) *(__half2*)&g_bufH[(size_t)r1 * 128 + col] = __floats2half2_rn(d[j][2], d[j][3]);
    }

    // fused attention logits (fp32 accumulators)
#pragma unroll
    for (int hd = 0; hd < 8; hd++) {
        float ss0 = 0.f, ds0 = 0.f, ss1 = 0.f, ds1 = 0.f;
#pragma unroll
        for (int jj = 0; jj < 2; jj++) {
            int j = hd * 2 + jj;
            int c = jj * 8 + 2 * q;
            float as0 = a_src[hd * CH + c], as1 = a_src[hd * CH + c + 1];
            float ad0 = a_dst[hd * CH + c], ad1 = a_dst[hd * CH + c + 1];
            ss0 += d[j][0] * as0 + d[j][1] * as1;
            ds0 += d[j][0] * ad0 + d[j][1] * ad1;
            ss1 += d[j][2] * as0 + d[j][3] * as1;
            ds1 += d[j][2] * ad0 + d[j][3] * ad1;
        }
        ss0 += __shfl_xor_sync(0xffffffffu, ss0, 1);
        ss0 += __shfl_xor_sync(0xffffffffu, ss0, 2);
        ds0 += __shfl_xor_sync(0xffffffffu, ds0, 1);
        ds0 += __shfl_xor_sync(0xffffffffu, ds0, 2);
        ss1 += __shfl_xor_sync(0xffffffffu, ss1, 1);
        ss1 += __shfl_xor_sync(0xffffffffu, ss1, 2);
        ds1 += __shfl_xor_sync(0xffffffffu, ds1, 1);
        ds1 += __shfl_xor_sync(0xffffffffu, ds1, 2);
        if (q == 0) {
            if (r0 < M) { g_alsrc[r0 * 8 + hd] = ss0; g_aldst[r0 * 8 + hd] = ds0; }
            if (r1 < M) { g_alsrc[r1 * 8 + hd] = ss1; g_aldst[r1 * 8 + hd] = ds1; }
        }
    }
}

// ---------------- per-node softmax + aggregation (lean loop, fp16 gather) ----------
__device__ __forceinline__ float4 hload4(int s, int lane) {
    uint2 raw = *(const uint2*)&g_bufH[(size_t)s * FEAT + lane * 4];
    float2 f0 = __half22float2(*(__half2*)&raw.x);
    float2 f1 = __half22float2(*(__half2*)&raw.y);
    return make_float4(f0.x, f0.y, f1.x, f1.y);
}

// MODE 0: g_bufB = elu(agg + bias)                      (layers 1,2)
// MODE 1: outp = mean_heads + b; fused anomaly head + block-level graph-sum
// NOTE: agg grid covers exactly N_NODES warps (6250 blocks x 8) -> no early return.
template <int MODE>
__global__ void k_agg(const float* __restrict__ bias, float* __restrict__ outp,
                      const float* __restrict__ an_w1, const float* __restrict__ an_b1,
                      const float* __restrict__ an_w2, const float* __restrict__ an_b2) {
    __shared__ float bsum[16];
    if (MODE == 1) {
        if (threadIdx.x < 16) bsum[threadIdx.x] = 0.f;
        __syncthreads();
    }
    int gw = (blockIdx.x * blockDim.x + threadIdx.x) >> 5;
    int lane = threadIdx.x & 31;
    int d = gw;
    const int beg = g_rowptr[d], end = g_rowptr[d + 1];
    const int head = lane >> 2;

    const float adst = g_aldst[d * 8 + head];
    float den;
    float4 acc;
    {   // self loop
        float p = __expf(lrelu02(g_alsrc[d * 8 + head] + adst));
        den = p;
        float4 hv = hload4(d, lane);
        acc.x = hv.x * p; acc.y = hv.y * p; acc.z = hv.z * p; acc.w = hv.w * p;
    }
    int i = beg;
    for (; i + 4 <= end; i += 4) {
        int s0 = g_col[i], s1 = g_col[i + 1], s2 = g_col[i + 2], s3 = g_col[i + 3];
        float a0 = g_alsrc[s0 * 8 + head];
        float a1 = g_alsrc[s1 * 8 + head];
        float a2 = g_alsrc[s2 * 8 + head];
        float a3 = g_alsrc[s3 * 8 + head];
        float4 h0 = hload4(s0, lane);
        float4 h1 = hload4(s1, lane);
        float4 h2 = hload4(s2, lane);
        float4 h3 = hload4(s3, lane);
        float p0 = __expf(lrelu02(a0 + adst));
        float p1 = __expf(lrelu02(a1 + adst));
        float p2 = __expf(lrelu02(a2 + adst));
        float p3 = __expf(lrelu02(a3 + adst));
        den += (p0 + p1) + (p2 + p3);
        acc.x += h0.x * p0 + h1.x * p1 + h2.x * p2 + h3.x * p3;
        acc.y += h0.y * p0 + h1.y * p1 + h2.y * p2 + h3.y * p3;
        acc.z += h0.z * p0 + h1.z * p1 + h2.z * p2 + h3.z * p3;
        acc.w += h0.w * p0 + h1.w * p1 + h2.w * p2 + h3.w * p3;
    }
    for (; i < end; i++) {
        int s = g_col[i];
        float p = __expf(lrelu02(g_alsrc[s * 8 + head] + adst));
        den += p;
        float4 hv = hload4(s, lane);
        acc.x += hv.x * p; acc.y += hv.y * p; acc.z += hv.z * p; acc.w += hv.w * p;
    }
    float inv = 1.f / den;
    acc.x *= inv; acc.y *= inv; acc.z *= inv; acc.w *= inv;

    if (MODE == 0) {
        float4 bb = *(const float4*)&bias[lane * 4];
        acc.x = elu1(acc.x + bb.x);
        acc.y = elu1(acc.y + bb.y);
        acc.z = elu1(acc.z + bb.z);
        acc.w = elu1(acc.w + bb.w);
        *(float4*)&g_bufB[(size_t)d * FEAT + lane * 4] = acc;
    } else {
#pragma unroll
        for (int off = 4; off <= 16; off <<= 1) {
            acc.x += __shfl_xor_sync(0xffffffffu, acc.x, off);
            acc.y += __shfl_xor_sync(0xffffffffu, acc.y, off);
            acc.z += __shfl_xor_sync(0xffffffffu, acc.z, off);
            acc.w += __shfl_xor_sync(0xffffffffu, acc.w, off);
        }
        float4 bb = *(const float4*)&bias[(lane & 3) * 4];
        float4 r;
        r.x = acc.x * 0.125f + bb.x;
        r.y = acc.y * 0.125f + bb.y;
        r.z = acc.z * 0.125f + bb.z;
        r.w = acc.w * 0.125f + bb.w;
        if (lane < 4) {
            *(float4*)&outp[(size_t)d * CH + lane * 4] = r;
            // block-level graph-sum accumulation (smem atomics)
            atomicAdd(&bsum[lane * 4 + 0], r.x);
            atomicAdd(&bsum[lane * 4 + 1], r.y);
            atomicAdd(&bsum[lane * 4 + 2], r.z);
            atomicAdd(&bsum[lane * 4 + 3], r.w);
        }

        // fused anomaly head: 16 -> 32 relu -> 1 sigmoid
        float hv[16];
#pragma unroll
        for (int c = 0; c < 16; c++) {
            float comp = ((c & 3) == 0) ? r.x : ((c & 3) == 1) ? r.y
                        : ((c & 3) == 2) ? r.z : r.w;
            hv[c] = __shfl_sync(0xffffffffu, comp, c >> 2);
        }
        float t = an_b1[lane];
#pragma unroll
        for (int c = 0; c < 16; c++) t += hv[c] * an_w1[c * 32 + lane];
        float contrib = fmaxf(t, 0.f) * an_w2[lane];
#pragma unroll
        for (int off = 16; off >= 1; off >>= 1)
            contrib += __shfl_xor_sync(0xffffffffu, contrib, off);
        if (lane == 0)
            outp[800000 + d] = 1.f / (1.f + __expf(-(contrib + an_b2[0])));

        __syncthreads();
        if (threadIdx.x < 16) atomicAdd(&g_gsum[threadIdx.x], bsum[threadIdx.x]);
    }
}

// ---------------- graph classifier ----------------
__global__ void k_final(const float* __restrict__ w1, const float* __restrict__ b1,
                        const float* __restrict__ w2, const float* __restrict__ b2,
                        float* __restrict__ out) {
    __shared__ float emb[16];
    __shared__ float hid[64];
    int t = threadIdx.x;
    if (t < 16) {
        float e = g_gsum[t] * (1.f / (float)N_NODES);
        emb[t] = e;
        out[850000 + t] = e;
    }
    __syncthreads();
    float s = b1[t];
#pragma unroll
    for (int c = 0; c < 16; c++) s += emb[c] * w1[c * 64 + t];
    hid[t] = fmaxf(s, 0.f);
    __syncthreads();
    if (t < 2) {
        float r = b2[t];
#pragma unroll
        for (int u = 0; u < 64; u++) r += hid[u] * w2[u * 2 + t];
        out[850016 + t] = r;
    }
}

// ---------------- launch ----------------
extern "C" void kernel_launch(void* const* d_in, const int* in_sizes, int n_in,
                              void* d_out, int out_size) {
    const float* x      = (const float*)d_in[0];
    const void*  ei     = d_in[1];
    const float* W1     = (const float*)d_in[2];
    const float* a1s    = (const float*)d_in[3];
    const float* a1d    = (const float*)d_in[4];
    const float* b1     = (const float*)d_in[5];
    const float* W2     = (const float*)d_in[6];
    const float* a2s    = (const float*)d_in[7];
    const float* a2d    = (const float*)d_in[8];
    const float* b2     = (const float*)d_in[9];
    const float* W3     = (const float*)d_in[10];
    const float* a3s    = (const float*)d_in[11];
    const float* a3d    = (const float*)d_in[12];
    const float* b3     = (const float*)d_in[13];
    const float* cls_w1 = (const float*)d_in[14];
    const float* cls_b1 = (const float*)d_in[15];
    const float* cls_w2 = (const float*)d_in[16];
    const float* cls_b2 = (const float*)d_in[17];
    const float* an_w1  = (const float*)d_in[18];
    const float* an_b1  = (const float*)d_in[19];
    const float* an_w2  = (const float*)d_in[20];
    const float* an_b2  = (const float*)d_in[21];
    float* out = (float*)d_out;

    const int TB = 256;
    const int nodeBlocks = (N_NODES + TB - 1) / TB;
    const int edgeBlocks = (N_EDGES + TB - 1) / TB;
    const int aggBlocks  = (N_NODES * 32) / TB;            // 6250, exact
    const int gemmBlocks = (N_NODES + 127) / 128;          // 391
    const int nchunks    = (N_NODES + 1023) / 1024;

    // layer 1 (gemm1 kept in absolute launch slot #4 for profiling)
    k_packW<<<64, TB>>>(W1, 256);
    k_zero<<<nodeBlocks, TB>>>((const unsigned int*)ei);
    k_count<<<edgeBlocks, TB>>>(ei);
    k_gemm<0><<<gemmBlocks, TB>>>(x, a1s, a1d, N_NODES, 256);   // profiled
    k_scan1<<<nchunks, 1024>>>();
    k_scan3<<<nodeBlocks, TB>>>();
    k_scatter<<<edgeBlocks, TB>>>(ei);
    k_agg<0><<<aggBlocks, TB>>>(b1, nullptr, nullptr, nullptr, nullptr, nullptr);

    // layer 2
    k_packW<<<32, TB>>>(W2, 128);
    k_gemm<1><<<gemmBlocks, TB>>>(nullptr, a2s, a2d, N_NODES, 128);
    k_agg<0><<<aggBlocks, TB>>>(b2, nullptr, nullptr, nullptr, nullptr, nullptr);

    // layer 3 (agg<1> also accumulates the graph mean)
    k_packW<<<32, TB>>>(W3, 128);
    k_gemm<1><<<gemmBlocks, TB>>>(nullptr, a3s, a3d, N_NODES, 128);
    k_agg<1><<<aggBlocks, TB>>>(b3, out, an_w1, an_b1, an_w2, an_b2);

    // graph classifier
    k_final<<<1, 64>>>(cls_w1, cls_b1, cls_w2, cls_b2, out);
}